// round 6
// baseline (speedup 1.0000x reference)
#include <cuda_runtime.h>
#include <cstdint>

#define BB 2048
#define DD 512
#define HH 1024
#define SS 100
#define KTOP 51

// Scratch (device globals — no allocation allowed)
__device__ float g_eps_mean[BB * DD];
__device__ float g_h[(size_t)BB * HH];
__device__ float g_op[BB * DD];

// ---- packed fp32x2 helpers (FFMA2 — only reachable via PTX, see SASS_QUICKREF)
__device__ __forceinline__ unsigned long long pack2(float lo, float hi) {
    unsigned long long r;
    asm("mov.b64 %0, {%1, %2};" : "=l"(r) : "f"(lo), "f"(hi));
    return r;
}
__device__ __forceinline__ unsigned long long ffma2(unsigned long long a,
                                                    unsigned long long b,
                                                    unsigned long long c) {
    unsigned long long d;
    asm("fma.rn.f32x2 %0, %1, %2, %3;" : "=l"(d) : "l"(a), "l"(b), "l"(c));
    return d;
}
__device__ __forceinline__ void unpack2(unsigned long long v, float& lo, float& hi) {
    asm("mov.b64 {%0, %1}, %2;" : "=f"(lo), "=f"(hi) : "l"(v));
}

// ---------------------------------------------------------------------------
// Kernel 1: eps_mean[b,d] = mean_s eps[s,b,d]   (419MB -> 4MB, HBM-bound)
// ---------------------------------------------------------------------------
__global__ __launch_bounds__(256) void eps_mean_kernel(const float4* __restrict__ eps) {
    const int i = blockIdx.x * blockDim.x + threadIdx.x;   // 0 .. BB*DD/4-1
    const int n4 = (BB * DD) / 4;
    const float4* p = eps + i;
    float4 a0 = make_float4(0.f, 0.f, 0.f, 0.f);
    float4 a1 = a0, a2 = a0, a3 = a0;
#pragma unroll 1
    for (int s = 0; s < SS; s += 4) {
        float4 v0 = p[(size_t)(s + 0) * n4];
        float4 v1 = p[(size_t)(s + 1) * n4];
        float4 v2 = p[(size_t)(s + 2) * n4];
        float4 v3 = p[(size_t)(s + 3) * n4];
        a0.x += v0.x; a0.y += v0.y; a0.z += v0.z; a0.w += v0.w;
        a1.x += v1.x; a1.y += v1.y; a1.z += v1.z; a1.w += v1.w;
        a2.x += v2.x; a2.y += v2.y; a2.z += v2.z; a2.w += v2.w;
        a3.x += v3.x; a3.y += v3.y; a3.z += v3.z; a3.w += v3.w;
    }
    const float inv = 1.0f / (float)SS;
    float4 r;
    r.x = (a0.x + a1.x + a2.x + a3.x) * inv;
    r.y = (a0.y + a1.y + a2.y + a3.y) * inv;
    r.z = (a0.z + a1.z + a2.z + a3.z) * inv;
    r.w = (a0.w + a1.w + a2.w + a3.w) * inv;
    reinterpret_cast<float4*>(g_eps_mean)[i] = r;
}

// ---------------------------------------------------------------------------
// Kernel 2: h[m,n] = relu(sum_k batch[m,k] * W1[n,k] + b1[n])
//   M=2048, N=1024, K=512.  BM=128, BN=64, BK=16, TM=8, TN=4, 256 threads.
//   Inner loop uses packed FFMA2: m-dim packed (A pairs native), B broadcast.
// ---------------------------------------------------------------------------
__global__ __launch_bounds__(256) void gemm1_relu_kernel(const float* __restrict__ A,
                                                         const float* __restrict__ W,
                                                         const float* __restrict__ bias) {
    const int K = DD, N = HH;
    __shared__ __align__(16) float As[16][132];   // [k][m], padded (row = 528B, 16B-mult)
    __shared__ __align__(16) float Bs[16][68];    // [k][n], padded (row = 272B, 16B-mult)

    const int t  = threadIdx.x;
    const int tx = t & 15;          // n-dim
    const int ty = t >> 4;          // m-dim
    const int m0 = blockIdx.y * 128;
    const int n0 = blockIdx.x * 64;

    // acc2[ip][j]: packed pair (m = ty*8+2ip, ty*8+2ip+1) x column j
    unsigned long long acc2[4][4];
    const unsigned long long z = pack2(0.f, 0.f);
#pragma unroll
    for (int i = 0; i < 4; i++)
#pragma unroll
        for (int j = 0; j < 4; j++) acc2[i][j] = z;

    for (int k0 = 0; k0 < K; k0 += 16) {
        // Load A tile 128x16 (transposed store): 512 float4, 2/thread
#pragma unroll
        for (int i = 0; i < 2; i++) {
            int lin = t + i * 256;
            int row = lin >> 2;
            int kq  = (lin & 3) << 2;
            float4 v = *reinterpret_cast<const float4*>(A + (size_t)(m0 + row) * K + k0 + kq);
            As[kq + 0][row] = v.x; As[kq + 1][row] = v.y;
            As[kq + 2][row] = v.z; As[kq + 3][row] = v.w;
        }
        // Load W tile 64x16: 256 float4, 1/thread
        {
            int row = t >> 2;
            int kq  = (t & 3) << 2;
            float4 v = *reinterpret_cast<const float4*>(W + (size_t)(n0 + row) * K + k0 + kq);
            Bs[kq + 0][row] = v.x; Bs[kq + 1][row] = v.y;
            Bs[kq + 2][row] = v.z; Bs[kq + 3][row] = v.w;
        }
        __syncthreads();
#pragma unroll
        for (int kk = 0; kk < 16; kk++) {
            // A m-pairs load natively as packed 64-bit lanes (16B-aligned)
            ulonglong2 a01 = *reinterpret_cast<const ulonglong2*>(&As[kk][ty * 8]);
            ulonglong2 a23 = *reinterpret_cast<const ulonglong2*>(&As[kk][ty * 8 + 4]);
            unsigned long long ap[4] = {a01.x, a01.y, a23.x, a23.y};
            float4 b = *reinterpret_cast<const float4*>(&Bs[kk][tx * 4]);
            unsigned long long bb[4] = {pack2(b.x, b.x), pack2(b.y, b.y),
                                        pack2(b.z, b.z), pack2(b.w, b.w)};
#pragma unroll
            for (int i = 0; i < 4; i++)
#pragma unroll
                for (int j = 0; j < 4; j++)
                    acc2[i][j] = ffma2(ap[i], bb[j], acc2[i][j]);
        }
        __syncthreads();
    }

    float acc[8][4];
#pragma unroll
    for (int ip = 0; ip < 4; ip++)
#pragma unroll
        for (int j = 0; j < 4; j++)
            unpack2(acc2[ip][j], acc[2 * ip][j], acc[2 * ip + 1][j]);

    float4 bvec = *reinterpret_cast<const float4*>(bias + n0 + tx * 4);
    float bb[4] = {bvec.x, bvec.y, bvec.z, bvec.w};
#pragma unroll
    for (int i = 0; i < 8; i++) {
        int m = m0 + ty * 8 + i;
        float4 o;
        o.x = fmaxf(acc[i][0] + bb[0], 0.f);
        o.y = fmaxf(acc[i][1] + bb[1], 0.f);
        o.z = fmaxf(acc[i][2] + bb[2], 0.f);
        o.w = fmaxf(acc[i][3] + bb[3], 0.f);
        *reinterpret_cast<float4*>(g_h + (size_t)m * N + n0 + tx * 4) = o;
    }
}

// ---------------------------------------------------------------------------
// Kernel 3: dual GEMM + fused epilogue
//   mu = h@W21^T + b21 ; lv = h@W22^T + b22
//   op = (mu + eps_mean*exp(0.5*lv)) * (batch != 0)
//   M=2048, N=512, K=1024.  BM=64, BN=64, BK=16, TM=4, TN=4, 256 threads.
//   Inner loop: n-dim packed (B pairs native), A broadcast.
// ---------------------------------------------------------------------------
__global__ __launch_bounds__(256) void gemm2_fused_kernel(const float* __restrict__ W21,
                                                          const float* __restrict__ b21,
                                                          const float* __restrict__ W22,
                                                          const float* __restrict__ b22,
                                                          const float* __restrict__ batch) {
    const int K = HH;
    __shared__ __align__(16) float As[16][68];
    __shared__ __align__(16) float B1s[16][68];
    __shared__ __align__(16) float B2s[16][68];

    const int t  = threadIdx.x;
    const int tx = t & 15;
    const int ty = t >> 4;
    const int m0 = blockIdx.y * 64;
    const int n0 = blockIdx.x * 64;

    // accm2[i][jp]: row (ty*4+i) x packed column pair (tx*4+2jp, +2jp+1)
    unsigned long long accm2[4][2], accv2[4][2];
    const unsigned long long z = pack2(0.f, 0.f);
#pragma unroll
    for (int i = 0; i < 4; i++)
#pragma unroll
        for (int j = 0; j < 2; j++) { accm2[i][j] = z; accv2[i][j] = z; }

    const int row = t >> 2;
    const int kq  = (t & 3) << 2;

    for (int k0 = 0; k0 < K; k0 += 16) {
        {
            float4 v = *reinterpret_cast<const float4*>(g_h + (size_t)(m0 + row) * K + k0 + kq);
            As[kq + 0][row] = v.x; As[kq + 1][row] = v.y;
            As[kq + 2][row] = v.z; As[kq + 3][row] = v.w;
        }
        {
            float4 v = *reinterpret_cast<const float4*>(W21 + (size_t)(n0 + row) * K + k0 + kq);
            B1s[kq + 0][row] = v.x; B1s[kq + 1][row] = v.y;
            B1s[kq + 2][row] = v.z; B1s[kq + 3][row] = v.w;
        }
        {
            float4 v = *reinterpret_cast<const float4*>(W22 + (size_t)(n0 + row) * K + k0 + kq);
            B2s[kq + 0][row] = v.x; B2s[kq + 1][row] = v.y;
            B2s[kq + 2][row] = v.z; B2s[kq + 3][row] = v.w;
        }
        __syncthreads();
#pragma unroll
        for (int kk = 0; kk < 16; kk++) {
            float4 a = *reinterpret_cast<const float4*>(&As[kk][ty * 4]);
            unsigned long long ab[4] = {pack2(a.x, a.x), pack2(a.y, a.y),
                                        pack2(a.z, a.z), pack2(a.w, a.w)};
            ulonglong2 b1p = *reinterpret_cast<const ulonglong2*>(&B1s[kk][tx * 4]);
            ulonglong2 b2p = *reinterpret_cast<const ulonglong2*>(&B2s[kk][tx * 4]);
            unsigned long long b1[2] = {b1p.x, b1p.y};
            unsigned long long b2[2] = {b2p.x, b2p.y};
#pragma unroll
            for (int i = 0; i < 4; i++)
#pragma unroll
                for (int jp = 0; jp < 2; jp++) {
                    accm2[i][jp] = ffma2(ab[i], b1[jp], accm2[i][jp]);
                    accv2[i][jp] = ffma2(ab[i], b2[jp], accv2[i][jp]);
                }
        }
        __syncthreads();
    }

    float4 c1 = *reinterpret_cast<const float4*>(b21 + n0 + tx * 4);
    float4 c2 = *reinterpret_cast<const float4*>(b22 + n0 + tx * 4);
    float b1a[4] = {c1.x, c1.y, c1.z, c1.w};
    float b2a[4] = {c2.x, c2.y, c2.z, c2.w};

#pragma unroll
    for (int i = 0; i < 4; i++) {
        int m = m0 + ty * 4 + i;
        float accm[4], accv[4];
        unpack2(accm2[i][0], accm[0], accm[1]);
        unpack2(accm2[i][1], accm[2], accm[3]);
        unpack2(accv2[i][0], accv[0], accv[1]);
        unpack2(accv2[i][1], accv[2], accv[3]);

        float4 emv = *reinterpret_cast<const float4*>(g_eps_mean + (size_t)m * DD + n0 + tx * 4);
        float4 btv = *reinterpret_cast<const float4*>(batch + (size_t)m * DD + n0 + tx * 4);
        float emr[4] = {emv.x, emv.y, emv.z, emv.w};
        float btr[4] = {btv.x, btv.y, btv.z, btv.w};
        float o[4];
#pragma unroll
        for (int j = 0; j < 4; j++) {
            float mu = accm[j] + b1a[j];
            float lv = accv[j] + b2a[j];
            float val = mu + emr[j] * expf(0.5f * lv);   // expf (not __expf): top-k boundary safety
            if (btr[j] == 0.f) val = 0.f;
            o[j] = val;
        }
        float4 ov = {o[0], o[1], o[2], o[3]};
        *reinterpret_cast<float4*>(g_op + (size_t)m * DD + n0 + tx * 4) = ov;
    }
}

// ---------------------------------------------------------------------------
// Kernel 4: per-row top-k (k=51 of 512) mask, jax tie-breaking (lowest index)
//   One block of 512 threads per row; bitonic sort values in shared.
// ---------------------------------------------------------------------------
__global__ __launch_bounds__(512) void topk_kernel(float* __restrict__ out) {
    __shared__ float sv[DD];
    __shared__ float so[DD];
    const int row = blockIdx.x;
    const int tid = threadIdx.x;

    float v = g_op[(size_t)row * DD + tid];
    sv[tid] = v;
    so[tid] = v;
    __syncthreads();

    // bitonic ascending sort of sv
    for (int ksz = 2; ksz <= DD; ksz <<= 1) {
        for (int j = ksz >> 1; j > 0; j >>= 1) {
            int l = tid ^ j;
            if (l > tid) {
                bool up = ((tid & ksz) == 0);
                float a = sv[tid], b = sv[l];
                if ((a > b) == up) { sv[tid] = b; sv[l] = a; }
            }
            __syncthreads();
        }
    }

    float thr = sv[DD - KTOP];                 // 51st largest
    int cgt = __syncthreads_count(v > thr);    // strictly-greater count
    int extra = KTOP - cgt;                    // ties at thr to keep (lowest idx first)

    bool keep = (v > thr);
    if (!keep && v == thr && extra > 0) {
        int rank = 0;
        for (int j = 0; j < tid; j++) rank += (so[j] == thr) ? 1 : 0;
        keep = (rank < extra);
    }
    out[(size_t)row * DD + tid] = keep ? v : 0.f;
}

// ---------------------------------------------------------------------------
extern "C" void kernel_launch(void* const* d_in, const int* in_sizes, int n_in,
                              void* d_out, int out_size) {
    (void)in_sizes; (void)n_in; (void)out_size;
    const float* batch = (const float*)d_in[0];
    const float* W1    = (const float*)d_in[1];
    const float* b1    = (const float*)d_in[2];
    const float* W21   = (const float*)d_in[3];
    const float* b21   = (const float*)d_in[4];
    const float* W22   = (const float*)d_in[5];
    const float* b22   = (const float*)d_in[6];
    const float* eps   = (const float*)d_in[7];
    float* out = (float*)d_out;

    // 1) eps mean: BB*DD/4 float4 elements
    {
        int n4 = (BB * DD) / 4;
        eps_mean_kernel<<<n4 / 256, 256>>>(reinterpret_cast<const float4*>(eps));
    }
    // 2) GEMM1: h = relu(batch @ W1^T + b1)
    {
        dim3 grid(HH / 64, BB / 128);
        gemm1_relu_kernel<<<grid, 256>>>(batch, W1, b1);
    }
    // 3) dual GEMM + fused epilogue -> g_op
    {
        dim3 grid(DD / 64, BB / 64);
        gemm2_fused_kernel<<<grid, 256>>>(W21, b21, W22, b22, batch);
    }
    // 4) per-row top-k mask -> out
    topk_kernel<<<BB, DD>>>(out);
}

// round 7
// speedup vs baseline: 1.0914x; 1.0914x over previous
#include <cuda_runtime.h>
#include <cstdint>

#define BB 2048
#define DD 512
#define HH 1024
#define SS 100
#define KTOP 51

// Scratch (device globals — no allocation allowed)
__device__ float g_eps_mean[BB * DD];
__device__ float g_h[(size_t)BB * HH];
__device__ float g_op[BB * DD];

// ---- packed fp32x2 helpers (FFMA2 — only reachable via PTX, see SASS_QUICKREF)
__device__ __forceinline__ unsigned long long pack2(float lo, float hi) {
    unsigned long long r;
    asm("mov.b64 %0, {%1, %2};" : "=l"(r) : "f"(lo), "f"(hi));
    return r;
}
__device__ __forceinline__ unsigned long long ffma2(unsigned long long a,
                                                    unsigned long long b,
                                                    unsigned long long c) {
    unsigned long long d;
    asm("fma.rn.f32x2 %0, %1, %2, %3;" : "=l"(d) : "l"(a), "l"(b), "l"(c));
    return d;
}
__device__ __forceinline__ void unpack2(unsigned long long v, float& lo, float& hi) {
    asm("mov.b64 {%0, %1}, %2;" : "=f"(lo), "=f"(hi) : "l"(v));
}

// ---------------------------------------------------------------------------
// Fused Kernel 1: eps_mean (HBM-bound) + GEMM1 (FMA-bound) in one grid.
//   1280 blocks, 256 threads. Blocks with (b%5==4) do a gemm1 tile (256 of
//   them = 16x16 tile grid); the rest (1024) do the eps reduction. Interleaved
//   so every wave has both kinds -> HBM pipe and FMA pipe overlap.
// ---------------------------------------------------------------------------
__global__ __launch_bounds__(256) void fused_eps_gemm1_kernel(const float4* __restrict__ eps,
                                                              const float* __restrict__ A,
                                                              const float* __restrict__ W,
                                                              const float* __restrict__ bias) {
    __shared__ __align__(16) float As[16][132];   // [k][m], row 528B (16B-mult)
    __shared__ __align__(16) float Bs[16][68];    // [k][n], row 272B (16B-mult)

    const int b = blockIdx.x;
    const int t = threadIdx.x;

    if ((b % 5) != 4) {
        // ---------------- eps_mean part: e in 0..1023 ----------------
        const int e = (b / 5) * 4 + (b % 5);
        const int i = e * 256 + t;                 // 0 .. BB*DD/4-1
        const int n4 = (BB * DD) / 4;
        const float4* p = eps + i;
        float4 a0 = make_float4(0.f, 0.f, 0.f, 0.f);
        float4 a1 = a0, a2 = a0, a3 = a0;
#pragma unroll 1
        for (int s = 0; s < SS; s += 4) {
            float4 v0 = p[(size_t)(s + 0) * n4];
            float4 v1 = p[(size_t)(s + 1) * n4];
            float4 v2 = p[(size_t)(s + 2) * n4];
            float4 v3 = p[(size_t)(s + 3) * n4];
            a0.x += v0.x; a0.y += v0.y; a0.z += v0.z; a0.w += v0.w;
            a1.x += v1.x; a1.y += v1.y; a1.z += v1.z; a1.w += v1.w;
            a2.x += v2.x; a2.y += v2.y; a2.z += v2.z; a2.w += v2.w;
            a3.x += v3.x; a3.y += v3.y; a3.z += v3.z; a3.w += v3.w;
        }
        const float inv = 1.0f / (float)SS;
        float4 r;
        r.x = (a0.x + a1.x + a2.x + a3.x) * inv;
        r.y = (a0.y + a1.y + a2.y + a3.y) * inv;
        r.z = (a0.z + a1.z + a2.z + a3.z) * inv;
        r.w = (a0.w + a1.w + a2.w + a3.w) * inv;
        reinterpret_cast<float4*>(g_eps_mean)[i] = r;
        return;
    }

    // ---------------- gemm1 part: g in 0..255 -> 16x16 tile grid ----------------
    // h[m,n] = relu(sum_k A[m,k]*W[n,k] + bias[n]); M=2048,N=1024,K=512
    // BM=128, BN=64, BK=16, TM=8 (packed x2), TN=4; FFMA2 inner loop.
    const int g  = b / 5;
    const int K = DD, N = HH;
    const int tx = t & 15;          // n-dim
    const int ty = t >> 4;          // m-dim
    const int m0 = (g >> 4) * 128;
    const int n0 = (g & 15) * 64;

    unsigned long long acc2[4][4];
    const unsigned long long z = pack2(0.f, 0.f);
#pragma unroll
    for (int i = 0; i < 4; i++)
#pragma unroll
        for (int j = 0; j < 4; j++) acc2[i][j] = z;

    for (int k0 = 0; k0 < K; k0 += 16) {
#pragma unroll
        for (int i = 0; i < 2; i++) {
            int lin = t + i * 256;
            int row = lin >> 2;
            int kq  = (lin & 3) << 2;
            float4 v = *reinterpret_cast<const float4*>(A + (size_t)(m0 + row) * K + k0 + kq);
            As[kq + 0][row] = v.x; As[kq + 1][row] = v.y;
            As[kq + 2][row] = v.z; As[kq + 3][row] = v.w;
        }
        {
            int row = t >> 2;
            int kq  = (t & 3) << 2;
            float4 v = *reinterpret_cast<const float4*>(W + (size_t)(n0 + row) * K + k0 + kq);
            Bs[kq + 0][row] = v.x; Bs[kq + 1][row] = v.y;
            Bs[kq + 2][row] = v.z; Bs[kq + 3][row] = v.w;
        }
        __syncthreads();
#pragma unroll
        for (int kk = 0; kk < 16; kk++) {
            ulonglong2 a01 = *reinterpret_cast<const ulonglong2*>(&As[kk][ty * 8]);
            ulonglong2 a23 = *reinterpret_cast<const ulonglong2*>(&As[kk][ty * 8 + 4]);
            unsigned long long ap[4] = {a01.x, a01.y, a23.x, a23.y};
            float4 bv = *reinterpret_cast<const float4*>(&Bs[kk][tx * 4]);
            unsigned long long bb[4] = {pack2(bv.x, bv.x), pack2(bv.y, bv.y),
                                        pack2(bv.z, bv.z), pack2(bv.w, bv.w)};
#pragma unroll
            for (int i = 0; i < 4; i++)
#pragma unroll
                for (int j = 0; j < 4; j++)
                    acc2[i][j] = ffma2(ap[i], bb[j], acc2[i][j]);
        }
        __syncthreads();
    }

    float acc[8][4];
#pragma unroll
    for (int ip = 0; ip < 4; ip++)
#pragma unroll
        for (int j = 0; j < 4; j++)
            unpack2(acc2[ip][j], acc[2 * ip][j], acc[2 * ip + 1][j]);

    float4 bvec = *reinterpret_cast<const float4*>(bias + n0 + tx * 4);
    float bbv[4] = {bvec.x, bvec.y, bvec.z, bvec.w};
#pragma unroll
    for (int i = 0; i < 8; i++) {
        int m = m0 + ty * 8 + i;
        float4 o;
        o.x = fmaxf(acc[i][0] + bbv[0], 0.f);
        o.y = fmaxf(acc[i][1] + bbv[1], 0.f);
        o.z = fmaxf(acc[i][2] + bbv[2], 0.f);
        o.w = fmaxf(acc[i][3] + bbv[3], 0.f);
        *reinterpret_cast<float4*>(g_h + (size_t)m * N + n0 + tx * 4) = o;
    }
}

// ---------------------------------------------------------------------------
// Kernel 2: dual GEMM + fused epilogue
//   mu = h@W21^T + b21 ; lv = h@W22^T + b22
//   op = (mu + eps_mean*exp(0.5*lv)) * (batch != 0)
//   M=2048, N=512, K=1024.  BM=64, BN=64, BK=16; FFMA2 (n-dim packed).
// ---------------------------------------------------------------------------
__global__ __launch_bounds__(256) void gemm2_fused_kernel(const float* __restrict__ W21,
                                                          const float* __restrict__ b21,
                                                          const float* __restrict__ W22,
                                                          const float* __restrict__ b22,
                                                          const float* __restrict__ batch) {
    const int K = HH;
    __shared__ __align__(16) float As[16][68];
    __shared__ __align__(16) float B1s[16][68];
    __shared__ __align__(16) float B2s[16][68];

    const int t  = threadIdx.x;
    const int tx = t & 15;
    const int ty = t >> 4;
    const int m0 = blockIdx.y * 64;
    const int n0 = blockIdx.x * 64;

    unsigned long long accm2[4][2], accv2[4][2];
    const unsigned long long z = pack2(0.f, 0.f);
#pragma unroll
    for (int i = 0; i < 4; i++)
#pragma unroll
        for (int j = 0; j < 2; j++) { accm2[i][j] = z; accv2[i][j] = z; }

    const int row = t >> 2;
    const int kq  = (t & 3) << 2;

    for (int k0 = 0; k0 < K; k0 += 16) {
        {
            float4 v = *reinterpret_cast<const float4*>(g_h + (size_t)(m0 + row) * K + k0 + kq);
            As[kq + 0][row] = v.x; As[kq + 1][row] = v.y;
            As[kq + 2][row] = v.z; As[kq + 3][row] = v.w;
        }
        {
            float4 v = *reinterpret_cast<const float4*>(W21 + (size_t)(n0 + row) * K + k0 + kq);
            B1s[kq + 0][row] = v.x; B1s[kq + 1][row] = v.y;
            B1s[kq + 2][row] = v.z; B1s[kq + 3][row] = v.w;
        }
        {
            float4 v = *reinterpret_cast<const float4*>(W22 + (size_t)(n0 + row) * K + k0 + kq);
            B2s[kq + 0][row] = v.x; B2s[kq + 1][row] = v.y;
            B2s[kq + 2][row] = v.z; B2s[kq + 3][row] = v.w;
        }
        __syncthreads();
#pragma unroll
        for (int kk = 0; kk < 16; kk++) {
            float4 a = *reinterpret_cast<const float4*>(&As[kk][ty * 4]);
            unsigned long long ab[4] = {pack2(a.x, a.x), pack2(a.y, a.y),
                                        pack2(a.z, a.z), pack2(a.w, a.w)};
            ulonglong2 b1p = *reinterpret_cast<const ulonglong2*>(&B1s[kk][tx * 4]);
            ulonglong2 b2p = *reinterpret_cast<const ulonglong2*>(&B2s[kk][tx * 4]);
            unsigned long long b1[2] = {b1p.x, b1p.y};
            unsigned long long b2[2] = {b2p.x, b2p.y};
#pragma unroll
            for (int i = 0; i < 4; i++)
#pragma unroll
                for (int jp = 0; jp < 2; jp++) {
                    accm2[i][jp] = ffma2(ab[i], b1[jp], accm2[i][jp]);
                    accv2[i][jp] = ffma2(ab[i], b2[jp], accv2[i][jp]);
                }
        }
        __syncthreads();
    }

    float4 c1 = *reinterpret_cast<const float4*>(b21 + n0 + tx * 4);
    float4 c2 = *reinterpret_cast<const float4*>(b22 + n0 + tx * 4);
    float b1a[4] = {c1.x, c1.y, c1.z, c1.w};
    float b2a[4] = {c2.x, c2.y, c2.z, c2.w};

#pragma unroll
    for (int i = 0; i < 4; i++) {
        int m = m0 + ty * 4 + i;
        float accm[4], accv[4];
        unpack2(accm2[i][0], accm[0], accm[1]);
        unpack2(accm2[i][1], accm[2], accm[3]);
        unpack2(accv2[i][0], accv[0], accv[1]);
        unpack2(accv2[i][1], accv[2], accv[3]);

        float4 emv = *reinterpret_cast<const float4*>(g_eps_mean + (size_t)m * DD + n0 + tx * 4);
        float4 btv = *reinterpret_cast<const float4*>(batch + (size_t)m * DD + n0 + tx * 4);
        float emr[4] = {emv.x, emv.y, emv.z, emv.w};
        float btr[4] = {btv.x, btv.y, btv.z, btv.w};
        float o[4];
#pragma unroll
        for (int j = 0; j < 4; j++) {
            float mu = accm[j] + b1a[j];
            float lv = accv[j] + b2a[j];
            float val = mu + emr[j] * expf(0.5f * lv);   // expf: top-k boundary safety
            if (btr[j] == 0.f) val = 0.f;
            o[j] = val;
        }
        float4 ov = {o[0], o[1], o[2], o[3]};
        *reinterpret_cast<float4*>(g_op + (size_t)m * DD + n0 + tx * 4) = ov;
    }
}

// ---------------------------------------------------------------------------
// Kernel 3: per-row top-k via 4-pass radix select (8-bit digits) on
// monotonic float keys. ~16 barriers vs 45 for bitonic; O(n) work.
// Tie-break: strictly-greater kept, ties at threshold by lowest index.
// ---------------------------------------------------------------------------
__global__ __launch_bounds__(512) void topk_kernel(float* __restrict__ out) {
    __shared__ unsigned hist[256];
    __shared__ unsigned sk[DD];      // keys, for tie ranking
    __shared__ unsigned wt[8];       // per-warp bin totals
    __shared__ unsigned sh_sel;      // selected digit this pass
    __shared__ unsigned sh_want;     // remaining rank within selected digit

    const int row = blockIdx.x;
    const int tid = threadIdx.x;
    const int lane = tid & 31;
    const int w = tid >> 5;

    float v = g_op[(size_t)row * DD + tid];
    unsigned u = __float_as_uint(v);
    unsigned key = (u & 0x80000000u) ? ~u : (u | 0x80000000u);  // monotonic
    sk[tid] = key;

    unsigned want = KTOP;
    unsigned prefix = 0, prefmask = 0;

#pragma unroll
    for (int shift = 24; shift >= 0; shift -= 8) {
        if (tid < 256) hist[tid] = 0;
        __syncthreads();
        bool cand = ((key & prefmask) == prefix);
        if (cand) atomicAdd(&hist[(key >> shift) & 255u], 1u);
        __syncthreads();

        // suffix-sum over 256 bins: warps 0..7 own 32 bins each
        unsigned h = (tid < 256) ? hist[tid] : 0u;
        unsigned s = h;   // inclusive suffix within warp's bins
#pragma unroll
        for (int off = 1; off < 32; off <<= 1) {
            unsigned tt = __shfl_down_sync(0xffffffffu, s, off);
            if (lane + off < 32) s += tt;
        }
        if (tid < 256 && lane == 0) wt[w] = s;  // warp total (suffix from lane 0)
        __syncthreads();
        if (tid < 256) {
            unsigned hi = 0;
#pragma unroll
            for (int ww = 0; ww < 8; ww++)
                if (ww > w) hi += wt[ww];
            unsigned S = s + hi;          // suffix sum from this bin to 255
            unsigned Sn = S - h;          // suffix from next bin
            if (S >= want && Sn < want) { // unique crossing
                sh_sel = (unsigned)tid;
                sh_want = want - Sn;
            }
        }
        __syncthreads();
        prefix  |= (sh_sel << shift);
        prefmask |= (255u << shift);
        want = sh_want;
        __syncthreads();   // protect sh_sel/sh_want before next pass overwrites
    }

    const unsigned thr_key = prefix;                // exact key of k-th largest
    bool gt = (key > thr_key);
    int cgt = __syncthreads_count(gt);              // strictly-greater count
    int extra = KTOP - cgt;                         // ties to keep (lowest idx)

    bool keep = gt;
    if (!keep && key == thr_key && extra > 0) {     // rare path
        int rank = 0;
        for (int j = 0; j < tid; j++) rank += (sk[j] == thr_key) ? 1 : 0;
        keep = (rank < extra);
    }
    out[(size_t)row * DD + tid] = keep ? v : 0.f;
}

// ---------------------------------------------------------------------------
extern "C" void kernel_launch(void* const* d_in, const int* in_sizes, int n_in,
                              void* d_out, int out_size) {
    (void)in_sizes; (void)n_in; (void)out_size;
    const float* batch = (const float*)d_in[0];
    const float* W1    = (const float*)d_in[1];
    const float* b1    = (const float*)d_in[2];
    const float* W21   = (const float*)d_in[3];
    const float* b21   = (const float*)d_in[4];
    const float* W22   = (const float*)d_in[5];
    const float* b22   = (const float*)d_in[6];
    const float* eps   = (const float*)d_in[7];
    float* out = (float*)d_out;

    // 1) fused: eps mean (1024 blocks) + gemm1 (256 blocks), interleaved mod 5
    fused_eps_gemm1_kernel<<<1280, 256>>>(reinterpret_cast<const float4*>(eps),
                                          batch, W1, b1);
    // 2) dual GEMM + fused epilogue -> g_op
    {
        dim3 grid(DD / 64, BB / 64);
        gemm2_fused_kernel<<<grid, 256>>>(W21, b21, W22, b22, batch);
    }
    // 3) per-row top-k mask -> out
    topk_kernel<<<BB, DD>>>(out);
}

// round 11
// speedup vs baseline: 1.3060x; 1.1966x over previous
#include <cuda_runtime.h>
#include <cstdint>

#define BB 2048
#define DD 512
#define HH 1024
#define SS 100
#define KTOP 51

// Scratch (device globals — no allocation allowed)
__device__ float g_h[(size_t)BB * HH];
__device__ float g_op[BB * DD];

// ---- packed fp32x2 helpers (FFMA2 — only reachable via PTX, see SASS_QUICKREF)
__device__ __forceinline__ unsigned long long pack2(float lo, float hi) {
    unsigned long long r;
    asm("mov.b64 %0, {%1, %2};" : "=l"(r) : "f"(lo), "f"(hi));
    return r;
}
__device__ __forceinline__ unsigned long long ffma2(unsigned long long a,
                                                    unsigned long long b,
                                                    unsigned long long c) {
    unsigned long long d;
    asm("fma.rn.f32x2 %0, %1, %2, %3;" : "=l"(d) : "l"(a), "l"(b), "l"(c));
    return d;
}
__device__ __forceinline__ void unpack2(unsigned long long v, float& lo, float& hi) {
    asm("mov.b64 {%0, %1}, %2;" : "=f"(lo), "=f"(hi) : "l"(v));
}

// ---------------------------------------------------------------------------
// Kernel 1: h[m,n] = relu(sum_k batch[m,k] * W1[n,k] + b1[n])
//   M=2048, N=1024, K=512.  BM=128, BN=64, BK=16; FFMA2 (m-dim packed).
// ---------------------------------------------------------------------------
__global__ __launch_bounds__(256) void gemm1_relu_kernel(const float* __restrict__ A,
                                                         const float* __restrict__ W,
                                                         const float* __restrict__ bias) {
    const int K = DD, N = HH;
    __shared__ __align__(16) float As[16][132];
    __shared__ __align__(16) float Bs[16][68];

    const int t  = threadIdx.x;
    const int tx = t & 15;
    const int ty = t >> 4;
    const int m0 = blockIdx.y * 128;
    const int n0 = blockIdx.x * 64;

    unsigned long long acc2[4][4];
    const unsigned long long z = pack2(0.f, 0.f);
#pragma unroll
    for (int i = 0; i < 4; i++)
#pragma unroll
        for (int j = 0; j < 4; j++) acc2[i][j] = z;

    for (int k0 = 0; k0 < K; k0 += 16) {
#pragma unroll
        for (int i = 0; i < 2; i++) {
            int lin = t + i * 256;
            int row = lin >> 2;
            int kq  = (lin & 3) << 2;
            float4 v = *reinterpret_cast<const float4*>(A + (size_t)(m0 + row) * K + k0 + kq);
            As[kq + 0][row] = v.x; As[kq + 1][row] = v.y;
            As[kq + 2][row] = v.z; As[kq + 3][row] = v.w;
        }
        {
            int row = t >> 2;
            int kq  = (t & 3) << 2;
            float4 v = *reinterpret_cast<const float4*>(W + (size_t)(n0 + row) * K + k0 + kq);
            Bs[kq + 0][row] = v.x; Bs[kq + 1][row] = v.y;
            Bs[kq + 2][row] = v.z; Bs[kq + 3][row] = v.w;
        }
        __syncthreads();
#pragma unroll
        for (int kk = 0; kk < 16; kk++) {
            ulonglong2 a01 = *reinterpret_cast<const ulonglong2*>(&As[kk][ty * 8]);
            ulonglong2 a23 = *reinterpret_cast<const ulonglong2*>(&As[kk][ty * 8 + 4]);
            unsigned long long ap[4] = {a01.x, a01.y, a23.x, a23.y};
            float4 bv = *reinterpret_cast<const float4*>(&Bs[kk][tx * 4]);
            unsigned long long bb[4] = {pack2(bv.x, bv.x), pack2(bv.y, bv.y),
                                        pack2(bv.z, bv.z), pack2(bv.w, bv.w)};
#pragma unroll
            for (int i = 0; i < 4; i++)
#pragma unroll
                for (int j = 0; j < 4; j++)
                    acc2[i][j] = ffma2(ap[i], bb[j], acc2[i][j]);
        }
        __syncthreads();
    }

    float acc[8][4];
#pragma unroll
    for (int ip = 0; ip < 4; ip++)
#pragma unroll
        for (int j = 0; j < 4; j++)
            unpack2(acc2[ip][j], acc[2 * ip][j], acc[2 * ip + 1][j]);

    float4 bvec = *reinterpret_cast<const float4*>(bias + n0 + tx * 4);
    float bbv[4] = {bvec.x, bvec.y, bvec.z, bvec.w};
#pragma unroll
    for (int i = 0; i < 8; i++) {
        int m = m0 + ty * 8 + i;
        float4 o;
        o.x = fmaxf(acc[i][0] + bbv[0], 0.f);
        o.y = fmaxf(acc[i][1] + bbv[1], 0.f);
        o.z = fmaxf(acc[i][2] + bbv[2], 0.f);
        o.w = fmaxf(acc[i][3] + bbv[3], 0.f);
        *reinterpret_cast<float4*>(g_h + (size_t)m * N + n0 + tx * 4) = o;
    }
}

// ---------------------------------------------------------------------------
// Kernel 2: dual GEMM + INLINE eps-mean + fused epilogue
//   mu = h@W21^T + b21 ; lv = h@W22^T + b22
//   emean[b,d] = mean_s eps[s,b,d]   (streamed inside the k-loop, pipelined)
//   op = (mu + emean*exp(0.5*lv)) * (batch != 0)
//   M=2048, N=512, K=1024.  BM=64, BN=64, BK=16; FFMA2 (n-dim packed).
// ---------------------------------------------------------------------------
__global__ __launch_bounds__(256) void gemm2_fused_kernel(const float* __restrict__ W21,
                                                          const float* __restrict__ b21,
                                                          const float* __restrict__ W22,
                                                          const float* __restrict__ b22,
                                                          const float* __restrict__ batch,
                                                          const float* __restrict__ eps) {
    const int K = HH;
    __shared__ __align__(16) float As[16][68];
    __shared__ __align__(16) float B1s[16][68];
    __shared__ __align__(16) float B2s[16][68];

    const int t  = threadIdx.x;
    const int tx = t & 15;
    const int ty = t >> 4;
    const int m0 = blockIdx.y * 64;
    const int n0 = blockIdx.x * 64;

    unsigned long long accm2[4][2], accv2[4][2];
    const unsigned long long z = pack2(0.f, 0.f);
#pragma unroll
    for (int i = 0; i < 4; i++)
#pragma unroll
        for (int j = 0; j < 2; j++) { accm2[i][j] = z; accv2[i][j] = z; }

    // eps pipeline state
    const size_t eps_base = (size_t)(m0 + ty * 4) * DD + n0 + tx * 4;  // row stride DD, sample stride BB*DD
    float4 eacc[4];
#pragma unroll
    for (int i = 0; i < 4; i++) eacc[i] = make_float4(0.f, 0.f, 0.f, 0.f);
    float4 pf[8];   // 2 samples x 4 rows in flight
    {
        const float* p0 = eps + eps_base;                       // sample 0
        const float* p1 = eps + eps_base + (size_t)BB * DD;     // sample 1
#pragma unroll
        for (int i = 0; i < 4; i++) {
            pf[i]     = *reinterpret_cast<const float4*>(p0 + (size_t)i * DD);
            pf[4 + i] = *reinterpret_cast<const float4*>(p1 + (size_t)i * DD);
        }
    }

    const int row = t >> 2;
    const int kq  = (t & 3) << 2;

    for (int n = 0; n < 64; n++) {
        const int k0 = n * 16;
        {
            float4 v = *reinterpret_cast<const float4*>(g_h + (size_t)(m0 + row) * K + k0 + kq);
            As[kq + 0][row] = v.x; As[kq + 1][row] = v.y;
            As[kq + 2][row] = v.z; As[kq + 3][row] = v.w;
        }
        {
            float4 v = *reinterpret_cast<const float4*>(W21 + (size_t)(n0 + row) * K + k0 + kq);
            B1s[kq + 0][row] = v.x; B1s[kq + 1][row] = v.y;
            B1s[kq + 2][row] = v.z; B1s[kq + 3][row] = v.w;
        }
        {
            float4 v = *reinterpret_cast<const float4*>(W22 + (size_t)(n0 + row) * K + k0 + kq);
            B2s[kq + 0][row] = v.x; B2s[kq + 1][row] = v.y;
            B2s[kq + 2][row] = v.z; B2s[kq + 3][row] = v.w;
        }
        __syncthreads();
#pragma unroll
        for (int kk = 0; kk < 16; kk++) {
            float4 a = *reinterpret_cast<const float4*>(&As[kk][ty * 4]);
            unsigned long long ab[4] = {pack2(a.x, a.x), pack2(a.y, a.y),
                                        pack2(a.z, a.z), pack2(a.w, a.w)};
            ulonglong2 b1p = *reinterpret_cast<const ulonglong2*>(&B1s[kk][tx * 4]);
            ulonglong2 b2p = *reinterpret_cast<const ulonglong2*>(&B2s[kk][tx * 4]);
            unsigned long long b1[2] = {b1p.x, b1p.y};
            unsigned long long b2[2] = {b2p.x, b2p.y};
#pragma unroll
            for (int i = 0; i < 4; i++)
#pragma unroll
                for (int jp = 0; jp < 2; jp++) {
                    accm2[i][jp] = ffma2(ab[i], b1[jp], accm2[i][jp]);
                    accv2[i][jp] = ffma2(ab[i], b2[jp], accv2[i][jp]);
                }
        }
        __syncthreads();

        // eps pipeline: accumulate samples (2n, 2n+1) loaded last iter; issue (2n+2, 2n+3)
        if (n < 50) {
#pragma unroll
            for (int i = 0; i < 4; i++) {
                eacc[i].x += pf[i].x + pf[4 + i].x;
                eacc[i].y += pf[i].y + pf[4 + i].y;
                eacc[i].z += pf[i].z + pf[4 + i].z;
                eacc[i].w += pf[i].w + pf[4 + i].w;
            }
            if (n < 49) {
                const float* p0 = eps + eps_base + (size_t)(2 * n + 2) * BB * DD;
                const float* p1 = eps + eps_base + (size_t)(2 * n + 3) * BB * DD;
#pragma unroll
                for (int i = 0; i < 4; i++) {
                    pf[i]     = *reinterpret_cast<const float4*>(p0 + (size_t)i * DD);
                    pf[4 + i] = *reinterpret_cast<const float4*>(p1 + (size_t)i * DD);
                }
            }
        }
    }

    float4 c1 = *reinterpret_cast<const float4*>(b21 + n0 + tx * 4);
    float4 c2 = *reinterpret_cast<const float4*>(b22 + n0 + tx * 4);
    float b1a[4] = {c1.x, c1.y, c1.z, c1.w};
    float b2a[4] = {c2.x, c2.y, c2.z, c2.w};
    const float inv = 1.0f / (float)SS;

#pragma unroll
    for (int i = 0; i < 4; i++) {
        int m = m0 + ty * 4 + i;
        float accm[4], accv[4];
        unpack2(accm2[i][0], accm[0], accm[1]);
        unpack2(accm2[i][1], accm[2], accm[3]);
        unpack2(accv2[i][0], accv[0], accv[1]);
        unpack2(accv2[i][1], accv[2], accv[3]);

        float emr[4] = {eacc[i].x * inv, eacc[i].y * inv, eacc[i].z * inv, eacc[i].w * inv};
        float4 btv = *reinterpret_cast<const float4*>(batch + (size_t)m * DD + n0 + tx * 4);
        float btr[4] = {btv.x, btv.y, btv.z, btv.w};
        float o[4];
#pragma unroll
        for (int j = 0; j < 4; j++) {
            float mu = accm[j] + b1a[j];
            float lv = accv[j] + b2a[j];
            float val = mu + emr[j] * expf(0.5f * lv);   // expf: top-k boundary safety
            if (btr[j] == 0.f) val = 0.f;
            o[j] = val;
        }
        float4 ov = {o[0], o[1], o[2], o[3]};
        *reinterpret_cast<float4*>(g_op + (size_t)m * DD + n0 + tx * 4) = ov;
    }
}

// ---------------------------------------------------------------------------
// Kernel 3: per-row top-k via 4-pass radix select (8-bit digits) on
// monotonic float keys. Tie-break: strictly-greater kept, ties by lowest idx.
// ---------------------------------------------------------------------------
__global__ __launch_bounds__(512) void topk_kernel(float* __restrict__ out) {
    __shared__ unsigned hist[256];
    __shared__ unsigned sk[DD];
    __shared__ unsigned wt[8];
    __shared__ unsigned sh_sel;
    __shared__ unsigned sh_want;

    const int row = blockIdx.x;
    const int tid = threadIdx.x;
    const int lane = tid & 31;
    const int w = tid >> 5;

    float v = g_op[(size_t)row * DD + tid];
    unsigned u = __float_as_uint(v);
    unsigned key = (u & 0x80000000u) ? ~u : (u | 0x80000000u);  // monotonic
    sk[tid] = key;

    unsigned want = KTOP;
    unsigned prefix = 0, prefmask = 0;

#pragma unroll
    for (int shift = 24; shift >= 0; shift -= 8) {
        if (tid < 256) hist[tid] = 0;
        __syncthreads();
        bool cand = ((key & prefmask) == prefix);
        if (cand) atomicAdd(&hist[(key >> shift) & 255u], 1u);
        __syncthreads();

        unsigned h = (tid < 256) ? hist[tid] : 0u;
        unsigned s = h;
#pragma unroll
        for (int off = 1; off < 32; off <<= 1) {
            unsigned tt = __shfl_down_sync(0xffffffffu, s, off);
            if (lane + off < 32) s += tt;
        }
        if (tid < 256 && lane == 0) wt[w] = s;
        __syncthreads();
        if (tid < 256) {
            unsigned hi = 0;
#pragma unroll
            for (int ww = 0; ww < 8; ww++)
                if (ww > w) hi += wt[ww];
            unsigned S = s + hi;
            unsigned Sn = S - h;
            if (S >= want && Sn < want) {
                sh_sel = (unsigned)tid;
                sh_want = want - Sn;
            }
        }
        __syncthreads();
        prefix  |= (sh_sel << shift);
        prefmask |= (255u << shift);
        want = sh_want;
        __syncthreads();
    }

    const unsigned thr_key = prefix;
    bool gt = (key > thr_key);
    int cgt = __syncthreads_count(gt);
    int extra = KTOP - cgt;

    bool keep = gt;
    if (!keep && key == thr_key && extra > 0) {
        int rank = 0;
        for (int j = 0; j < tid; j++) rank += (sk[j] == thr_key) ? 1 : 0;
        keep = (rank < extra);
    }
    out[(size_t)row * DD + tid] = keep ? v : 0.f;
}

// ---------------------------------------------------------------------------
extern "C" void kernel_launch(void* const* d_in, const int* in_sizes, int n_in,
                              void* d_out, int out_size) {
    (void)in_sizes; (void)n_in; (void)out_size;
    const float* batch = (const float*)d_in[0];
    const float* W1    = (const float*)d_in[1];
    const float* b1    = (const float*)d_in[2];
    const float* W21   = (const float*)d_in[3];
    const float* b21   = (const float*)d_in[4];
    const float* W22   = (const float*)d_in[5];
    const float* b22   = (const float*)d_in[6];
    const float* eps   = (const float*)d_in[7];
    float* out = (float*)d_out;

    // 1) GEMM1: h = relu(batch @ W1^T + b1)
    {
        dim3 grid(HH / 64, BB / 128);
        gemm1_relu_kernel<<<grid, 256>>>(batch, W1, b1);
    }
    // 2) dual GEMM + inline eps-mean + fused epilogue -> g_op
    {
        dim3 grid(DD / 64, BB / 64);
        gemm2_fused_kernel<<<grid, 256>>>(W21, b21, W22, b22, batch, eps);
    }
    // 3) per-row top-k mask -> out
    topk_kernel<<<BB, DD>>>(out);
}